// round 5
// baseline (speedup 1.0000x reference)
#include <cuda_runtime.h>
#include <cuda_bf16.h>

// ---------------- problem constants ----------------
#define BATCH 256
#define FRAMES 256
#define IN_DIM 34
#define NJ3 51
#define DDIM 512
#define G4 2048            // 4*D
#define K0 608             // 34 (x) + 51 (pred) + 512 (h0) padded 597->608
#define K1 1024            // 512 (h0n) + 512 (h1prev)
#define GRID 128
#define THREADS 256
#define NT (GRID*THREADS)

// ---------------- device scratch (allowed: static __device__ arrays) ----------------
__device__ float g_W0t[K0*G4];        // packed [k][m] weights for gates0
__device__ float g_W1t[K1*G4];        // packed [k][m] weights for gates1
__device__ float g_bias0[G4];
__device__ float g_bias1[G4];
__device__ float g_initp[BATCH*96];   // init padded 85->96
__device__ float g_niW1p[96*DDIM];    // ni_W1 padded rows 85->96
__device__ float g_z1[BATCH*DDIM];
__device__ float g_z2[BATCH*1024];
__device__ float g_z3[BATCH*2048];
__device__ float g_X0[BATCH*K0];      // [b][k]: 0..33 x_t, 34..84 pred, 85..596 h0, pad
__device__ float g_X1[BATCH*K1];      // [b][k]: 0..511 h0n, 512..1023 h1prev
__device__ float g_c0[BATCH*DDIM];
__device__ float g_c1[BATCH*DDIM];
__device__ float g_gates0[BATCH*G4];
__device__ float g_gates1[BATCH*G4];

// barrier state (replay-safe: only relative generation compares)
__device__ unsigned int g_arrive;
__device__ volatile unsigned int g_release;

__device__ __forceinline__ void grid_sync() {
    __threadfence();            // order this thread's global writes device-wide
    __syncthreads();
    if (threadIdx.x == 0) {
        unsigned int gen = g_release;
        unsigned int prev = atomicAdd(&g_arrive, 1u);
        if (prev == gridDim.x - 1u) {
            g_arrive = 0u;
            __threadfence();
            g_release = gen + 1u;
        } else {
            while (g_release == gen) { __nanosleep(64); }
        }
        __threadfence();
    }
    __syncthreads();
}

__device__ __forceinline__ float sigf(float v)  { return 1.0f / (1.0f + __expf(-v)); }
__device__ __forceinline__ float tanhg(float v) { float e = __expf(2.0f*v); return 1.0f - 2.0f/(e + 1.0f); }

// ---------------- setup kernel 1: heavy (folded x-weight + bias0) ----------------
__global__ void k_setup_heavy(const float* __restrict__ embed_W,
                              const float* __restrict__ embed_b,
                              const float* __restrict__ Wih0,
                              const float* __restrict__ bih0,
                              const float* __restrict__ bhh0) {
    int idx = blockIdx.x * blockDim.x + threadIdx.x;
    const int TOT = 34*G4 + G4;
    for (; idx < TOT; idx += gridDim.x * blockDim.x) {
        if (idx < 34*G4) {
            int m = idx & 2047, j = idx >> 11;           // W0t[j][m] = sum_d embed_W[j][d]*Wih0[m][d]
            const float* wr = Wih0 + m*563;
            const float* er = embed_W + j*512;
            float s = 0.f;
            #pragma unroll 4
            for (int d = 0; d < 512; d++) s += er[d] * wr[d];
            g_W0t[j*G4 + m] = s;
        } else {
            int m = idx - 34*G4;                          // bias0 = bih0+bhh0+embed_b@Wx^T
            const float* wr = Wih0 + m*563;
            float s = bih0[m] + bhh0[m];
            #pragma unroll 4
            for (int d = 0; d < 512; d++) s += embed_b[d] * wr[d];
            g_bias0[m] = s;
        }
    }
}

// ---------------- setup kernel 2: packs/copies ----------------
__global__ void k_setup_copy(const float* __restrict__ x,
                             const float* __restrict__ init,
                             const float* __restrict__ Wih0,
                             const float* __restrict__ Whh0,
                             const float* __restrict__ Wih1,
                             const float* __restrict__ Whh1,
                             const float* __restrict__ bih1,
                             const float* __restrict__ bhh1,
                             const float* __restrict__ niW1) {
    const int S1 = 574*G4;            // W0t cols 34..607
    const int S2 = 1024*G4;           // W1t
    const int S3 = G4;                // bias1
    const int S4 = BATCH*96;          // initp
    const int S5 = 96*DDIM;           // niW1p
    const int S6 = BATCH*85;          // X0 cols 0..84 (x_0 | pred0)
    const int S7 = BATCH*11;          // X0 pad cols 597..607
    const int TOT = S1+S2+S3+S4+S5+S6+S7;
    int i = blockIdx.x * blockDim.x + threadIdx.x;
    for (; i < TOT; i += gridDim.x * blockDim.x) {
        int r = i;
        if (r < S1) {
            int m = r & 2047; int k = 34 + (r >> 11);
            float v;
            if (k < 85)       v = Wih0[m*563 + 512 + (k-34)];
            else if (k < 597) v = Whh0[m*512 + (k-85)];
            else              v = 0.f;
            g_W0t[k*G4 + m] = v;
            continue;
        }
        r -= S1;
        if (r < S2) {
            int m = r & 2047; int k = r >> 11;
            g_W1t[k*G4 + m] = (k < 512) ? Wih1[m*512 + k] : Whh1[m*512 + (k-512)];
            continue;
        }
        r -= S2;
        if (r < S3) { g_bias1[r] = bih1[r] + bhh1[r]; continue; }
        r -= S3;
        if (r < S4) { int b = r/96, j = r - b*96; g_initp[r] = (j < 85) ? init[b*85 + j] : 0.f; continue; }
        r -= S4;
        if (r < S5) { int k = r >> 9;  g_niW1p[r] = (k < 85) ? niW1[r] : 0.f; continue; }
        r -= S5;
        if (r < S6) {
            int b = r/85, j = r - b*85;
            g_X0[b*K0 + j] = (j < 34) ? x[(b*FRAMES)*IN_DIM + j] : init[b*85 + (j-34)];
            continue;
        }
        r -= S6;
        { int b = r/11, j = r - b*11; g_X0[b*K0 + 597 + j] = 0.f; }
    }
}

// ---------------- tiled GEMM: C[M,N] = A[M,K] @ B[K,N] (+bias, opt relu) ----------------
// A is mutable scratch -> __ldcg ; B is setup-written weights -> __ldg ; C scratch -> __stcg
// M%64==0, N%64==0, K%16==0, lda/ldb/ldc %4==0.
template<bool RELU>
__device__ __forceinline__ void gemm_nt(const float* __restrict__ A, int lda,
                                        const float* __restrict__ B, int ldb,
                                        float* __restrict__ C, int ldc,
                                        int M, int N, int K,
                                        const float* __restrict__ bias,
                                        float* sm) {
    float* As = sm;             // [16][68] transposed A tile
    float* Bs = sm + 16*68;     // [16][64]
    const int tid = threadIdx.x;
    const int nT = N >> 6;
    const int ntiles = (M >> 6) * nT;
    const int ar = tid >> 2, ac = (tid & 3) << 2;
    const int bk = tid >> 4, bn = (tid & 15) << 2;
    const int ty = tid >> 4, tx = tid & 15;
    for (int tile = blockIdx.x; tile < ntiles; tile += gridDim.x) {
        const int m0 = (tile / nT) << 6;
        const int n0 = (tile - (tile / nT) * nT) << 6;
        float4 acc0 = make_float4(0,0,0,0), acc1 = acc0, acc2 = acc0, acc3 = acc0;
        for (int k0 = 0; k0 < K; k0 += 16) {
            float4 va = __ldcg((const float4*)(A + (m0 + ar)*lda + k0 + ac));
            float4 vb = __ldg ((const float4*)(B + (k0 + bk)*ldb + n0 + bn));
            As[(ac+0)*68 + ar] = va.x;
            As[(ac+1)*68 + ar] = va.y;
            As[(ac+2)*68 + ar] = va.z;
            As[(ac+3)*68 + ar] = va.w;
            *(float4*)(Bs + bk*64 + bn) = vb;
            __syncthreads();
            #pragma unroll
            for (int kk = 0; kk < 16; kk++) {
                float4 a = *(const float4*)(As + kk*68 + (ty << 2));
                float4 b = *(const float4*)(Bs + kk*64 + (tx << 2));
                acc0.x += a.x*b.x; acc0.y += a.x*b.y; acc0.z += a.x*b.z; acc0.w += a.x*b.w;
                acc1.x += a.y*b.x; acc1.y += a.y*b.y; acc1.z += a.y*b.z; acc1.w += a.y*b.w;
                acc2.x += a.z*b.x; acc2.y += a.z*b.y; acc2.z += a.z*b.z; acc2.w += a.z*b.w;
                acc3.x += a.w*b.x; acc3.y += a.w*b.y; acc3.z += a.w*b.z; acc3.w += a.w*b.w;
            }
            __syncthreads();
        }
        float4 bb = __ldg((const float4*)(bias + n0 + (tx << 2)));
        float4 accs[4] = {acc0, acc1, acc2, acc3};
        #pragma unroll
        for (int i = 0; i < 4; i++) {
            float4 v = accs[i];
            v.x += bb.x; v.y += bb.y; v.z += bb.z; v.w += bb.w;
            if (RELU) { v.x = fmaxf(v.x, 0.f); v.y = fmaxf(v.y, 0.f);
                        v.z = fmaxf(v.z, 0.f); v.w = fmaxf(v.w, 0.f); }
            __stcg((float4*)(C + (m0 + (ty << 2) + i)*ldc + n0 + (tx << 2)), v);
        }
    }
}

// ---------------- persistent scan kernel ----------------
__global__ void __launch_bounds__(THREADS, 1)
k_persist(const float* __restrict__ x,
          const float* __restrict__ niW2, const float* __restrict__ niW3,
          const float* __restrict__ nb1,  const float* __restrict__ nb2,
          const float* __restrict__ nb3,
          const float* __restrict__ decW, const float* __restrict__ decb,
          float* __restrict__ out_pred, float* __restrict__ out_mc) {
    __shared__ float sm[16*68 + 16*64];
    const int gtid = blockIdx.x * THREADS + threadIdx.x;

    // ---- init network ----
    gemm_nt<true >(g_initp, 96,   g_niW1p, DDIM, g_z1, DDIM, BATCH, DDIM, 96,   nb1, sm);
    grid_sync();
    gemm_nt<true >(g_z1,   DDIM,  niW2,    1024, g_z2, 1024, BATCH, 1024, DDIM, nb2, sm);
    grid_sync();
    gemm_nt<false>(g_z2,   1024,  niW3,    2048, g_z3, 2048, BATCH, 2048, 1024, nb3, sm);
    grid_sync();
    for (int idx = gtid; idx < BATCH*DDIM; idx += NT) {
        int b = idx >> 9, d = idx & 511;
        const float* zr = g_z3 + b*2048;
        __stcg(&g_X0[b*K0 + 85 + d],        __ldcg(zr + d));          // h layer0
        __stcg(&g_X1[b*K1 + 512 + d],       __ldcg(zr + 512 + d));    // h layer1
        __stcg(&g_c0[idx],                  __ldcg(zr + 1024 + d));
        __stcg(&g_c1[idx],                  __ldcg(zr + 1536 + d));
    }
    grid_sync();

    // ---- scan ----
    for (int t = 0; t < FRAMES; t++) {
        // gates0 = X0 @ W0t + bias0
        gemm_nt<false>(g_X0, K0, g_W0t, G4, g_gates0, G4, BATCH, G4, K0, g_bias0, sm);
        grid_sync();
        // LSTM cell 0: h0n feeds BOTH the next step's gates0 (X0 h-slot)
        // and this step's gates1 (X1 low half).  <-- the round-2 bug was the
        // missing X0 update: h0 stayed frozen at its init value.
        for (int idx = gtid; idx < BATCH*DDIM; idx += NT) {
            int b = idx >> 9, d = idx & 511;
            const float* g0 = g_gates0 + b*G4;
            float ig = sigf (__ldcg(g0 + d));
            float fg = sigf (__ldcg(g0 + 512 + d));
            float gg = tanhg(__ldcg(g0 + 1024 + d));
            float og = sigf (__ldcg(g0 + 1536 + d));
            float c  = fg * __ldcg(&g_c0[idx]) + ig * gg;
            __stcg(&g_c0[idx], c);
            float h0n = og * tanhg(c);
            __stcg(&g_X1[b*K1 + d], h0n);            // input to gates1 (this step)
            __stcg(&g_X0[b*K0 + 85 + d], h0n);       // recurrent h0 (next step)  [FIX]
        }
        grid_sync();
        // gates1 = X1 @ W1t + bias1
        gemm_nt<false>(g_X1, K1, g_W1t, G4, g_gates1, G4, BATCH, G4, K1, g_bias1, sm);
        grid_sync();
        // LSTM cell 1 (+ motion_context h part)
        for (int idx = gtid; idx < BATCH*DDIM; idx += NT) {
            int b = idx >> 9, d = idx & 511;
            const float* g1 = g_gates1 + b*G4;
            float ig = sigf (__ldcg(g1 + d));
            float fg = sigf (__ldcg(g1 + 512 + d));
            float gg = tanhg(__ldcg(g1 + 1024 + d));
            float og = sigf (__ldcg(g1 + 1536 + d));
            float c  = fg * __ldcg(&g_c1[idx]) + ig * gg;
            __stcg(&g_c1[idx], c);
            float h = og * tanhg(c);
            __stcg(&g_X1[b*K1 + 512 + d], h);
            out_mc[((long)b*FRAMES + t)*563 + d] = h;
        }
        grid_sync();
        // decoder + output writes + x copy for next step (block -> 2 batch rows)
        {
            float* h1s = sm;                     // reuse smem (1024 floats)
            const int b0 = blockIdx.x << 1;
            for (int i = threadIdx.x; i < 1024; i += THREADS) {
                int bb = i >> 9, d = i & 511;
                h1s[i] = __ldcg(&g_X1[(b0 + bb)*K1 + 512 + d]);
            }
            __syncthreads();
            int bb = threadIdx.x >> 7, jj = threadIdx.x & 127;
            if (jj < NJ3) {
                int b = b0 + bb;
                float s = __ldg(&decb[jj]);
                const float* hr = h1s + (bb << 9);
                #pragma unroll 8
                for (int d = 0; d < 512; d++) s += hr[d] * __ldg(&decW[d*NJ3 + jj]);
                long bt = (long)b*FRAMES + t;
                out_pred[bt*NJ3 + jj] = s;
                out_mc[bt*563 + 512 + jj] = s;
                __stcg(&g_X0[b*K0 + 34 + jj], s);
            }
            if (t + 1 < FRAMES) {
                for (int i = threadIdx.x; i < 2*IN_DIM; i += THREADS) {
                    int bb2 = i / IN_DIM, j = i - bb2*IN_DIM;
                    int b = b0 + bb2;
                    __stcg(&g_X0[b*K0 + j], x[((long)b*FRAMES + t + 1)*IN_DIM + j]);
                }
            }
        }
        grid_sync();
    }
}

// ---------------- entry ----------------
extern "C" void kernel_launch(void* const* d_in, const int* in_sizes, int n_in,
                              void* d_out, int out_size) {
    const float* x       = (const float*)d_in[0];
    const float* init_   = (const float*)d_in[1];
    const float* embed_W = (const float*)d_in[2];
    const float* embed_b = (const float*)d_in[3];
    const float* ni_W1   = (const float*)d_in[4];
    const float* ni_b1   = (const float*)d_in[5];
    const float* ni_W2   = (const float*)d_in[6];
    const float* ni_b2   = (const float*)d_in[7];
    const float* ni_W3   = (const float*)d_in[8];
    const float* ni_b3   = (const float*)d_in[9];
    const float* Wih0    = (const float*)d_in[10];
    const float* Whh0    = (const float*)d_in[11];
    const float* bih0    = (const float*)d_in[12];
    const float* bhh0    = (const float*)d_in[13];
    const float* Wih1    = (const float*)d_in[14];
    const float* Whh1    = (const float*)d_in[15];
    const float* bih1    = (const float*)d_in[16];
    const float* bhh1    = (const float*)d_in[17];
    const float* dec_W   = (const float*)d_in[18];
    const float* dec_b   = (const float*)d_in[19];

    float* out_pred = (float*)d_out;                              // (256,256,17,3)
    float* out_mc   = out_pred + (long)BATCH*FRAMES*NJ3;          // (256,256,563)

    k_setup_heavy<<<280, 256>>>(embed_W, embed_b, Wih0, bih0, bhh0);
    k_setup_copy <<<2048, 256>>>(x, init_, Wih0, Whh0, Wih1, Whh1, bih1, bhh1, ni_W1);
    k_persist    <<<GRID, THREADS>>>(x, ni_W2, ni_W3, ni_b1, ni_b2, ni_b3,
                                     dec_W, dec_b, out_pred, out_mc);
}

// round 6
// speedup vs baseline: 1.4742x; 1.4742x over previous
#include <cuda_runtime.h>
#include <cuda_bf16.h>

// ---------------- problem constants ----------------
#define BATCH 256
#define FRAMES 256
#define IN_DIM 34
#define NJ3 51
#define DDIM 512
#define G4 2048            // 4*D
#define K0 608             // 34 (x) + 51 (pred) + 512 (h0) padded 597->608
#define K1 1024            // 512 (h0n) + 512 (h1prev)
#define GRID 128
#define THREADS 256
#define NT (GRID*THREADS)

// ---------------- device scratch ----------------
// Gate-interleaved weights: column m' = 4*d + gate   (gate: 0=i,1=f,2=g,3=o)
__device__ float g_W0t[K0*G4];
__device__ float g_W1t[K1*G4];
__device__ float g_bias0[G4];         // interleaved
__device__ float g_bias1[G4];         // interleaved
__device__ float g_initp[BATCH*96];
__device__ float g_niW1p[96*DDIM];
__device__ float g_z1[BATCH*DDIM];
__device__ float g_z2[BATCH*1024];
__device__ float g_z3[BATCH*2048];
// Ping-pong activation buffers (race-free with fused epilogues)
__device__ float g_X0[2][BATCH*K0];   // [b][k]: 0..33 x_t, 34..84 pred, 85..596 h0, pad
__device__ float g_X1[2][BATCH*K1];   // [b][k]: 0..511 h0n(this step), 512..1023 h1(prev)
__device__ float g_c0[BATCH*DDIM];
__device__ float g_c1[BATCH*DDIM];

// barrier state
__device__ unsigned int g_arrive;
__device__ volatile unsigned int g_release;

__device__ __forceinline__ void grid_sync() {
    __threadfence();
    __syncthreads();
    if (threadIdx.x == 0) {
        unsigned int gen = g_release;
        unsigned int prev = atomicAdd(&g_arrive, 1u);
        if (prev == gridDim.x - 1u) {
            g_arrive = 0u;
            __threadfence();
            g_release = gen + 1u;
        } else {
            while (g_release == gen) { __nanosleep(32); }
        }
        __threadfence();
    }
    __syncthreads();
}

__device__ __forceinline__ float sigf(float v)  { return 1.0f / (1.0f + __expf(-v)); }
__device__ __forceinline__ float tanhg(float v) { float e = __expf(2.0f*v); return 1.0f - 2.0f/(e + 1.0f); }

// ---------------- setup kernel 1: folded x-weight + bias0 (interleaved) ----------------
__global__ void k_setup_heavy(const float* __restrict__ embed_W,
                              const float* __restrict__ embed_b,
                              const float* __restrict__ Wih0,
                              const float* __restrict__ bih0,
                              const float* __restrict__ bhh0) {
    int idx = blockIdx.x * blockDim.x + threadIdx.x;
    const int TOT = 34*G4 + G4;
    for (; idx < TOT; idx += gridDim.x * blockDim.x) {
        if (idx < 34*G4) {
            int m = idx & 2047, j = idx >> 11;
            int mp = ((m & 511) << 2) | (m >> 9);        // interleave
            const float* wr = Wih0 + m*563;
            const float* er = embed_W + j*512;
            float s = 0.f;
            #pragma unroll 4
            for (int d = 0; d < 512; d++) s += er[d] * wr[d];
            g_W0t[j*G4 + mp] = s;
        } else {
            int m = idx - 34*G4;
            int mp = ((m & 511) << 2) | (m >> 9);
            const float* wr = Wih0 + m*563;
            float s = bih0[m] + bhh0[m];
            #pragma unroll 4
            for (int d = 0; d < 512; d++) s += embed_b[d] * wr[d];
            g_bias0[mp] = s;
        }
    }
}

// ---------------- setup kernel 2: packs/copies (interleaved weights) ----------------
__global__ void k_setup_copy(const float* __restrict__ x,
                             const float* __restrict__ init,
                             const float* __restrict__ Wih0,
                             const float* __restrict__ Whh0,
                             const float* __restrict__ Wih1,
                             const float* __restrict__ Whh1,
                             const float* __restrict__ bih1,
                             const float* __restrict__ bhh1,
                             const float* __restrict__ niW1) {
    const int S1 = 574*G4;            // W0t rows 34..607
    const int S2 = 1024*G4;           // W1t
    const int S3 = G4;                // bias1
    const int S4 = BATCH*96;          // initp
    const int S5 = 96*DDIM;           // niW1p
    const int S6 = BATCH*85;          // X0[0] cols 0..84 (x_0 | pred0)
    const int S7 = BATCH*22;          // X0 pad cols 597..607, both buffers
    const int TOT = S1+S2+S3+S4+S5+S6+S7;
    int i = blockIdx.x * blockDim.x + threadIdx.x;
    for (; i < TOT; i += gridDim.x * blockDim.x) {
        int r = i;
        if (r < S1) {
            int m = r & 2047; int k = 34 + (r >> 11);
            int mp = ((m & 511) << 2) | (m >> 9);
            float v;
            if (k < 85)       v = Wih0[m*563 + 512 + (k-34)];
            else if (k < 597) v = Whh0[m*512 + (k-85)];
            else              v = 0.f;
            g_W0t[k*G4 + mp] = v;
            continue;
        }
        r -= S1;
        if (r < S2) {
            int m = r & 2047; int k = r >> 11;
            int mp = ((m & 511) << 2) | (m >> 9);
            g_W1t[k*G4 + mp] = (k < 512) ? Wih1[m*512 + k] : Whh1[m*512 + (k-512)];
            continue;
        }
        r -= S2;
        if (r < S3) {
            int mp = ((r & 511) << 2) | (r >> 9);
            g_bias1[mp] = bih1[r] + bhh1[r]; continue;
        }
        r -= S3;
        if (r < S4) { int b = r/96, j = r - b*96; g_initp[r] = (j < 85) ? init[b*85 + j] : 0.f; continue; }
        r -= S4;
        if (r < S5) { int k = r >> 9;  g_niW1p[r] = (k < 85) ? niW1[r] : 0.f; continue; }
        r -= S5;
        if (r < S6) {
            int b = r/85, j = r - b*85;
            g_X0[0][b*K0 + j] = (j < 34) ? x[(b*FRAMES)*IN_DIM + j] : init[b*85 + (j-34)];
            continue;
        }
        r -= S6;
        { int b = r/22, jj = r - b*22; g_X0[jj/11][b*K0 + 597 + (jj%11)] = 0.f; }
    }
}

// ---------------- generic tiled GEMM (init MLP only) ----------------
template<bool RELU>
__device__ __forceinline__ void gemm_nt(const float* __restrict__ A, int lda,
                                        const float* __restrict__ B, int ldb,
                                        float* __restrict__ C, int ldc,
                                        int M, int N, int K,
                                        const float* __restrict__ bias,
                                        float* sm) {
    float* As = sm;             // [16][68]
    float* Bs = sm + 16*68;     // [16][64]
    const int tid = threadIdx.x;
    const int nT = N >> 6;
    const int ntiles = (M >> 6) * nT;
    const int ar = tid >> 2, ac = (tid & 3) << 2;
    const int bk = tid >> 4, bn = (tid & 15) << 2;
    const int ty = tid >> 4, tx = tid & 15;
    for (int tile = blockIdx.x; tile < ntiles; tile += gridDim.x) {
        const int m0 = (tile / nT) << 6;
        const int n0 = (tile - (tile / nT) * nT) << 6;
        float4 acc0 = make_float4(0,0,0,0), acc1 = acc0, acc2 = acc0, acc3 = acc0;
        for (int k0 = 0; k0 < K; k0 += 16) {
            float4 va = __ldcg((const float4*)(A + (m0 + ar)*lda + k0 + ac));
            float4 vb = __ldg ((const float4*)(B + (k0 + bk)*ldb + n0 + bn));
            As[(ac+0)*68 + ar] = va.x;
            As[(ac+1)*68 + ar] = va.y;
            As[(ac+2)*68 + ar] = va.z;
            As[(ac+3)*68 + ar] = va.w;
            *(float4*)(Bs + bk*64 + bn) = vb;
            __syncthreads();
            #pragma unroll
            for (int kk = 0; kk < 16; kk++) {
                float4 a = *(const float4*)(As + kk*68 + (ty << 2));
                float4 b = *(const float4*)(Bs + kk*64 + (tx << 2));
                acc0.x += a.x*b.x; acc0.y += a.x*b.y; acc0.z += a.x*b.z; acc0.w += a.x*b.w;
                acc1.x += a.y*b.x; acc1.y += a.y*b.y; acc1.z += a.y*b.z; acc1.w += a.y*b.w;
                acc2.x += a.z*b.x; acc2.y += a.z*b.y; acc2.z += a.z*b.z; acc2.w += a.z*b.w;
                acc3.x += a.w*b.x; acc3.y += a.w*b.y; acc3.z += a.w*b.z; acc3.w += a.w*b.w;
            }
            __syncthreads();
        }
        float4 bb = __ldg((const float4*)(bias + n0 + (tx << 2)));
        float4 accs[4] = {acc0, acc1, acc2, acc3};
        #pragma unroll
        for (int i = 0; i < 4; i++) {
            float4 v = accs[i];
            v.x += bb.x; v.y += bb.y; v.z += bb.z; v.w += bb.w;
            if (RELU) { v.x = fmaxf(v.x, 0.f); v.y = fmaxf(v.y, 0.f);
                        v.z = fmaxf(v.z, 0.f); v.w = fmaxf(v.w, 0.f); }
            __stcg((float4*)(C + (m0 + (ty << 2) + i)*ldc + n0 + (tx << 2)), v);
        }
    }
}

// ---------------- fused GEMM + LSTM-cell epilogue ----------------
// Computes gates = A @ W (+bias) for one 64x64 tile (tile == blockIdx.x; 128 tiles),
// then applies the LSTM cell directly: float4 acc = (i,f,g,o) for one d.
// Double-buffered smem k-tiles: one __syncthreads per k-iter.
template<int LAYER>
__device__ __forceinline__ void gemm_cell(const float* __restrict__ A, int lda, int K,
                                          const float* __restrict__ W,
                                          const float* __restrict__ bias,
                                          float* __restrict__ cArr,
                                          float* __restrict__ X0next,
                                          float* __restrict__ X1cur,
                                          float* __restrict__ X1next,
                                          float* __restrict__ out_mc, int t,
                                          float* sm) {
    const int tid = threadIdx.x;
    const int tile = blockIdx.x;              // exactly 128 tiles (4 x 32)
    const int m0 = (tile >> 5) << 6;
    const int n0 = (tile & 31) << 6;
    const int ar = tid >> 2, ac = (tid & 3) << 2;
    const int bk = tid >> 4, bn = (tid & 15) << 2;
    const int ty = tid >> 4, tx = tid & 15;

    float4 acc[4];
    acc[0] = make_float4(0,0,0,0); acc[1] = acc[0]; acc[2] = acc[0]; acc[3] = acc[0];

    // prologue: load k-tile 0 into buffer 0
    float4 va = __ldcg((const float4*)(A + (m0 + ar)*lda + ac));
    float4 vb = __ldg ((const float4*)(W + bk*G4 + n0 + bn));
    {
        float* As0 = sm;                 // buffers: As[2][16*68], Bs[2][16*64]
        float* Bs0 = sm + 2176;
        As0[(ac+0)*68 + ar] = va.x;
        As0[(ac+1)*68 + ar] = va.y;
        As0[(ac+2)*68 + ar] = va.z;
        As0[(ac+3)*68 + ar] = va.w;
        *(float4*)(Bs0 + bk*64 + bn) = vb;
    }
    __syncthreads();

    int p = 0;
    for (int k0 = 0; k0 < K; k0 += 16) {
        const bool pre = (k0 + 16 < K);
        if (pre) {
            va = __ldcg((const float4*)(A + (m0 + ar)*lda + (k0 + 16) + ac));
            vb = __ldg ((const float4*)(W + (k0 + 16 + bk)*G4 + n0 + bn));
        }
        const float* Asp = sm + p*1088;
        const float* Bsp = sm + 2176 + p*1024;
        #pragma unroll
        for (int kk = 0; kk < 16; kk++) {
            float4 a = *(const float4*)(Asp + kk*68 + (ty << 2));
            float4 b = *(const float4*)(Bsp + kk*64 + (tx << 2));
            acc[0].x += a.x*b.x; acc[0].y += a.x*b.y; acc[0].z += a.x*b.z; acc[0].w += a.x*b.w;
            acc[1].x += a.y*b.x; acc[1].y += a.y*b.y; acc[1].z += a.y*b.z; acc[1].w += a.y*b.w;
            acc[2].x += a.z*b.x; acc[2].y += a.z*b.y; acc[2].z += a.z*b.z; acc[2].w += a.z*b.w;
            acc[3].x += a.w*b.x; acc[3].y += a.w*b.y; acc[3].z += a.w*b.z; acc[3].w += a.w*b.w;
        }
        if (pre) {
            float* Asn = sm + (p^1)*1088;
            float* Bsn = sm + 2176 + (p^1)*1024;
            Asn[(ac+0)*68 + ar] = va.x;
            Asn[(ac+1)*68 + ar] = va.y;
            Asn[(ac+2)*68 + ar] = va.z;
            Asn[(ac+3)*68 + ar] = va.w;
            *(float4*)(Bsn + bk*64 + bn) = vb;
        }
        __syncthreads();
        p ^= 1;
    }

    // epilogue: LSTM cell on (i,f,g,o) quads
    float4 bb = __ldg((const float4*)(bias + n0 + (tx << 2)));
    const int dd = (n0 >> 2) + tx;            // hidden index for this thread's quad
    #pragma unroll
    for (int i = 0; i < 4; i++) {
        const int b = m0 + (ty << 2) + i;
        float ig = sigf (acc[i].x + bb.x);
        float fg = sigf (acc[i].y + bb.y);
        float gg = tanhg(acc[i].z + bb.z);
        float og = sigf (acc[i].w + bb.w);
        float c  = fg * cArr[b*DDIM + dd] + ig * gg;   // c: CTA-private across steps
        cArr[b*DDIM + dd] = c;
        float h = og * tanhg(c);
        if (LAYER == 0) {
            __stcg(&X1cur [b*K1 + dd], h);             // input to gates1 (this step)
            __stcg(&X0next[b*K0 + 85 + dd], h);        // recurrent h0 (next step)
        } else {
            __stcg(&X1next[b*K1 + 512 + dd], h);       // recurrent h1 (next step)
            out_mc[((long)b*FRAMES + t)*563 + dd] = h; // motion_context h part
        }
    }
}

// ---------------- persistent scan kernel ----------------
__global__ void __launch_bounds__(THREADS, 1)
k_persist(const float* __restrict__ x,
          const float* __restrict__ niW2, const float* __restrict__ niW3,
          const float* __restrict__ nb1,  const float* __restrict__ nb2,
          const float* __restrict__ nb3,
          const float* __restrict__ decW, const float* __restrict__ decb,
          float* __restrict__ out_pred, float* __restrict__ out_mc) {
    __shared__ float sm[2*16*68 + 2*16*64];   // 4224 floats (fused GEMM double buffer)
    const int gtid = blockIdx.x * THREADS + threadIdx.x;

    // ---- init network ----
    gemm_nt<true >(g_initp, 96,   g_niW1p, DDIM, g_z1, DDIM, BATCH, DDIM, 96,   nb1, sm);
    grid_sync();
    gemm_nt<true >(g_z1,   DDIM,  niW2,    1024, g_z2, 1024, BATCH, 1024, DDIM, nb2, sm);
    grid_sync();
    gemm_nt<false>(g_z2,   1024,  niW3,    2048, g_z3, 2048, BATCH, 2048, 1024, nb3, sm);
    grid_sync();
    for (int idx = gtid; idx < BATCH*DDIM; idx += NT) {
        int b = idx >> 9, d = idx & 511;
        const float* zr = g_z3 + b*2048;
        __stcg(&g_X0[0][b*K0 + 85 + d],  __ldcg(zr + d));          // h0 init
        __stcg(&g_X1[0][b*K1 + 512 + d], __ldcg(zr + 512 + d));    // h1 init
        __stcg(&g_c0[idx],               __ldcg(zr + 1024 + d));
        __stcg(&g_c1[idx],               __ldcg(zr + 1536 + d));
    }
    grid_sync();

    // ---- scan: 3 grid syncs per step ----
    for (int t = 0; t < FRAMES; t++) {
        const int cur = t & 1, nxt = cur ^ 1;

        // phase A: gates0 GEMM + cell0 epilogue
        gemm_cell<0>(g_X0[cur], K0, K0, g_W0t, g_bias0, g_c0,
                     g_X0[nxt], g_X1[cur], nullptr, nullptr, t, sm);
        grid_sync();

        // phase B: gates1 GEMM + cell1 epilogue
        gemm_cell<1>(g_X1[cur], K1, K1, g_W1t, g_bias1, g_c1,
                     nullptr, nullptr, g_X1[nxt], out_mc, t, sm);
        grid_sync();

        // phase C: decoder + next-step x copy (block -> 2 batch rows)
        {
            float* h1s = sm;                     // reuse smem (1024 floats)
            const int b0 = blockIdx.x << 1;
            for (int i = threadIdx.x; i < 1024; i += THREADS) {
                int bb = i >> 9, d = i & 511;
                h1s[i] = __ldcg(&g_X1[nxt][(b0 + bb)*K1 + 512 + d]);
            }
            __syncthreads();
            int bb = threadIdx.x >> 7, jj = threadIdx.x & 127;
            if (jj < NJ3) {
                int b = b0 + bb;
                float s = __ldg(&decb[jj]);
                const float* hr = h1s + (bb << 9);
                #pragma unroll 8
                for (int d = 0; d < 512; d++) s += hr[d] * __ldg(&decW[d*NJ3 + jj]);
                long bt = (long)b*FRAMES + t;
                out_pred[bt*NJ3 + jj] = s;
                out_mc[bt*563 + 512 + jj] = s;
                __stcg(&g_X0[nxt][b*K0 + 34 + jj], s);
            }
            if (t + 1 < FRAMES) {
                for (int i = threadIdx.x; i < 2*IN_DIM; i += THREADS) {
                    int bb2 = i / IN_DIM, j = i - bb2*IN_DIM;
                    int b = b0 + bb2;
                    __stcg(&g_X0[nxt][b*K0 + j], x[((long)b*FRAMES + t + 1)*IN_DIM + j]);
                }
            }
        }
        grid_sync();
    }
}

// ---------------- entry ----------------
extern "C" void kernel_launch(void* const* d_in, const int* in_sizes, int n_in,
                              void* d_out, int out_size) {
    const float* x       = (const float*)d_in[0];
    const float* init_   = (const float*)d_in[1];
    const float* embed_W = (const float*)d_in[2];
    const float* embed_b = (const float*)d_in[3];
    const float* ni_W1   = (const float*)d_in[4];
    const float* ni_b1   = (const float*)d_in[5];
    const float* ni_W2   = (const float*)d_in[6];
    const float* ni_b2   = (const float*)d_in[7];
    const float* ni_W3   = (const float*)d_in[8];
    const float* ni_b3   = (const float*)d_in[9];
    const float* Wih0    = (const float*)d_in[10];
    const float* Whh0    = (const float*)d_in[11];
    const float* bih0    = (const float*)d_in[12];
    const float* bhh0    = (const float*)d_in[13];
    const float* Wih1    = (const float*)d_in[14];
    const float* Whh1    = (const float*)d_in[15];
    const float* bih1    = (const float*)d_in[16];
    const float* bhh1    = (const float*)d_in[17];
    const float* dec_W   = (const float*)d_in[18];
    const float* dec_b   = (const float*)d_in[19];

    float* out_pred = (float*)d_out;                              // (256,256,17,3)
    float* out_mc   = out_pred + (long)BATCH*FRAMES*NJ3;          // (256,256,563)

    k_setup_heavy<<<280, 256>>>(embed_W, embed_b, Wih0, bih0, bhh0);
    k_setup_copy <<<2048, 256>>>(x, init_, Wih0, Whh0, Wih1, Whh1, bih1, bhh1, ni_W1);
    k_persist    <<<GRID, THREADS>>>(x, ni_W2, ni_W3, ni_b1, ni_b2, ni_b3,
                                     dec_W, dec_b, out_pred, out_mc);
}